// round 5
// baseline (speedup 1.0000x reference)
#include <cuda_runtime.h>
#include <math.h>
#include <stdint.h>

#define EMBED  1024
#define NHEADS 16
#define HDIM   64
#define BATCH  2
#define TQ     2048
#define TK     2048
#define MROWS  (BATCH*TQ)   // 4096

// Scratch (__device__ globals; allocation-free rule)
__device__ float g_Q  [(size_t)MROWS * EMBED];
__device__ float g_KV [(size_t)MROWS * 2 * EMBED];
__device__ float g_O  [(size_t)MROWS * EMBED];
__device__ float g_rq [(size_t)MROWS * EMBED];
__device__ float g_rc [(size_t)MROWS * EMBED];
__device__ float g_rWq [(size_t)EMBED * EMBED];
__device__ float g_rWkv[(size_t)EMBED * 2 * EMBED];
__device__ float g_rWo [(size_t)EMBED * EMBED];

// ---------------------------------------------------------------------------
__device__ __forceinline__ uint32_t f2tf(float f) {
    uint32_t u;
    asm("cvt.rna.tf32.f32 %0, %1;" : "=r"(u) : "f"(f));
    return u;
}
__device__ __forceinline__ float f2tf_f(float f) { return __uint_as_float(f2tf(f)); }

__device__ __forceinline__ void mma_tf32(float* d, const uint32_t* a, const uint32_t* b) {
    asm volatile(
        "mma.sync.aligned.m16n8k8.row.col.f32.tf32.tf32.f32 "
        "{%0,%1,%2,%3}, {%4,%5,%6,%7}, {%8,%9}, {%0,%1,%2,%3};"
        : "+f"(d[0]), "+f"(d[1]), "+f"(d[2]), "+f"(d[3])
        : "r"(a[0]), "r"(a[1]), "r"(a[2]), "r"(a[3]), "r"(b[0]), "r"(b[1]));
}

__device__ __forceinline__ void cpa16(uint32_t dst, const float* src) {
    asm volatile("cp.async.cg.shared.global [%0], [%1], 16;" :: "r"(dst), "l"(src));
}
__device__ __forceinline__ void cpa_commit() { asm volatile("cp.async.commit_group;"); }
__device__ __forceinline__ void cpa_wait1()  { asm volatile("cp.async.wait_group 1;"); }
__device__ __forceinline__ void cpa_wait0()  { asm volatile("cp.async.wait_group 0;"); }

// ---------------------------------------------------------------------------
// Fused pre-round pass over all 5 tensors (one launch).
// Segments (float4 counts): rq 1048576 | rc 1048576 | Wq 262144 | Wkv 524288 | Wo 262144
// ---------------------------------------------------------------------------
__global__ void round_all_kernel(
    const float4* __restrict__ q,  float4* __restrict__ dq,
    const float4* __restrict__ c,  float4* __restrict__ dc,
    const float4* __restrict__ wq, float4* __restrict__ dwq,
    const float4* __restrict__ wkv,float4* __restrict__ dwkv,
    const float4* __restrict__ wo, float4* __restrict__ dwo)
{
    int i = blockIdx.x * blockDim.x + threadIdx.x;      // 0 .. 3145727
    const float4* s; float4* d; int off;
    if      (i < 1048576)  { s = q;   d = dq;   off = 0; }
    else if (i < 2097152)  { s = c;   d = dc;   off = 1048576; }
    else if (i < 2359296)  { s = wq;  d = dwq;  off = 2097152; }
    else if (i < 2883584)  { s = wkv; d = dwkv; off = 2359296; }
    else                   { s = wo;  d = dwo;  off = 2883584; }
    int j = i - off;
    float4 v = s[j];
    float4 r = { f2tf_f(v.x), f2tf_f(v.y), f2tf_f(v.z), f2tf_f(v.w) };
    d[j] = r;
}

// ---------------------------------------------------------------------------
// Projection GEMM: 128x128 tile, BK=32, 256 thr, 3-stage cp.async ring.
// ---------------------------------------------------------------------------
#define GSTG 8704
#define GASZ 4608

template <bool ROUND>
__device__ __forceinline__ void gemm_body(
    float* smem,
    const float* __restrict__ A, const float* __restrict__ W,
    const float* __restrict__ bias, float* __restrict__ C,
    int N, int K, int row0, int col0, float oscale)
{
    const int tid    = threadIdx.x;
    const int lane   = tid & 31;
    const int wid    = tid >> 5;
    const int gid    = lane >> 2;
    const int tid4   = lane & 3;
    const int warp_m = wid & 1;
    const int warp_n = wid >> 1;
    const uint32_t sbase = (uint32_t)__cvta_generic_to_shared(smem);

    auto issue_stage = [&](int stage, int k0) {
        #pragma unroll
        for (int p = 0; p < 4; p++) {
            int idx = tid + p * 256;
            int r = idx >> 3, c4 = (idx & 7) << 2;
            cpa16(sbase + (uint32_t)(stage * GSTG + r * 36 + c4) * 4,
                  &A[(size_t)(row0 + r) * K + k0 + c4]);
            int rw = idx >> 5, cw = (idx & 31) << 2;
            cpa16(sbase + (uint32_t)(stage * GSTG + GASZ + rw * 128 + (cw ^ ((rw & 3) << 3))) * 4,
                  &W[(size_t)(k0 + rw) * N + col0 + cw]);
        }
        cpa_commit();
    };

    const int T = K / 32;
    issue_stage(0, 0);

    float acc[4][4][4] = {};

    for (int t = 0; t < T; t++) {
        if (t + 1 < T) { issue_stage((t + 1) % 3, (t + 1) * 32); cpa_wait1(); }
        else           { cpa_wait0(); }
        __syncthreads();

        const uint32_t* As = (const uint32_t*)smem + (t % 3) * GSTG;
        const uint32_t* Ws = As + GASZ;

        #pragma unroll
        for (int ks = 0; ks < 4; ks++) {
            const int k = ks * 8;
            uint32_t a[4][4];
            #pragma unroll
            for (int mi = 0; mi < 4; mi++) {
                int rb = warp_m * 64 + mi * 16;
                a[mi][0] = As[(rb + gid)     * 36 + k + tid4];
                a[mi][1] = As[(rb + gid + 8) * 36 + k + tid4];
                a[mi][2] = As[(rb + gid)     * 36 + k + tid4 + 4];
                a[mi][3] = As[(rb + gid + 8) * 36 + k + tid4 + 4];
            }
            uint32_t b[4][2];
            #pragma unroll
            for (int ni = 0; ni < 4; ni++) {
                int cb = warp_n * 32 + ni * 8;
                int r1 = k + tid4, r2 = k + tid4 + 4;
                b[ni][0] = Ws[r1 * 128 + ((cb + gid) ^ ((r1 & 3) << 3))];
                b[ni][1] = Ws[r2 * 128 + ((cb + gid) ^ ((r2 & 3) << 3))];
            }
            #pragma unroll
            for (int mi = 0; mi < 4; mi++)
                #pragma unroll
                for (int ni = 0; ni < 4; ni++)
                    mma_tf32(acc[mi][ni], a[mi], b[ni]);
        }
        __syncthreads();
    }

    #pragma unroll
    for (int mi = 0; mi < 4; mi++) {
        int row = row0 + warp_m * 64 + mi * 16 + gid;
        #pragma unroll
        for (int ni = 0; ni < 4; ni++) {
            int col = col0 + warp_n * 32 + ni * 8 + 2 * tid4;
            float b0 = bias[col], b1 = bias[col + 1];
            float x0 = acc[mi][ni][0] + b0, x1 = acc[mi][ni][1] + b1;
            float x2 = acc[mi][ni][2] + b0, x3 = acc[mi][ni][3] + b1;
            if (ROUND) {
                x0 = f2tf_f(x0 * oscale); x1 = f2tf_f(x1 * oscale);
                x2 = f2tf_f(x2 * oscale); x3 = f2tf_f(x3 * oscale);
            }
            float2 v0 = { x0, x1 }, v1 = { x2, x3 };
            *reinterpret_cast<float2*>(&C[(size_t)row       * N + col]) = v0;
            *reinterpret_cast<float2*>(&C[(size_t)(row + 8) * N + col]) = v1;
        }
    }
}

__global__ __launch_bounds__(256, 2) void qkv_proj_kernel(
    const float* __restrict__ query, const float* __restrict__ context,
    const float* __restrict__ Wq, const float* __restrict__ bq,
    const float* __restrict__ Wkv, const float* __restrict__ bkv,
    float* __restrict__ qbuf, float* __restrict__ kvbuf)
{
    extern __shared__ float smem[];
    const int row0 = blockIdx.y * 128;
    if (blockIdx.x < 8)
        gemm_body<true>(smem, query, Wq, bq, qbuf, EMBED, EMBED,
                        row0, blockIdx.x * 128, 0.125f);
    else
        gemm_body<true>(smem, context, Wkv, bkv, kvbuf, 2 * EMBED, EMBED,
                        row0, (blockIdx.x - 8) * 128, 1.0f);
}

__global__ __launch_bounds__(256, 2) void oproj_kernel(
    const float* __restrict__ A, const float* __restrict__ W,
    const float* __restrict__ bias, float* __restrict__ C)
{
    extern __shared__ float smem[];
    gemm_body<false>(smem, A, W, bias, C, EMBED, EMBED,
                     blockIdx.y * 128, blockIdx.x * 128, 1.0f);
}

// ---------------------------------------------------------------------------
// Flash attention: 128 thr = 4 warps. Each CTA handles 128 q-rows as TWO
// 64-row halves that share every KV stage (halves KV traffic, doubles MMA
// per barrier). Warp-local softmax; P buffer reused across halves
// (warp-private rows -> __syncwarp only).
// Smem (floats): Q0 4096 | Q1 4096 | P 4096 | KV 2 stages x 8192 = 28672
//   = 112 KB -> 2 CTA/SM.
// ---------------------------------------------------------------------------
__device__ __forceinline__ int asw(int r, int c) { return r * 64 + (c ^ ((r & 7) << 3)); }

#define AQ_OFF  0           // half h at AQ_OFF + h*4096
#define AP_OFF  8192
#define AKV_OFF 12288       // stage s: K at +s*8192, V at +s*8192+4096

__global__ __launch_bounds__(128, 2) void attn_tc_kernel(
    const float* __restrict__ Q, const float* __restrict__ KV, float* __restrict__ O)
{
    extern __shared__ float smem[];
    const uint32_t sbase = (uint32_t)__cvta_generic_to_shared(smem);

    const int tid  = threadIdx.x;
    const int lane = tid & 31;
    const int wid  = tid >> 5;
    const int gid  = lane >> 2;
    const int tid4 = lane & 3;
    const int rb   = wid * 16;
    const int bh   = blockIdx.y;
    const int b    = bh >> 4;
    const int h    = bh & 15;
    const int q0   = blockIdx.x * 128;

    auto issue_kv = [&](int stage, int kt) {
        #pragma unroll
        for (int p = 0; p < 8; p++) {
            int idx = tid + p * 128;
            int r = idx >> 4, c4 = (idx & 15) << 2;
            size_t rowb = (size_t)(b * TK + kt + r) * (2 * EMBED) + h * HDIM + c4;
            uint32_t d = sbase + (uint32_t)(AKV_OFF + stage * 8192 + asw(r, c4)) * 4;
            cpa16(d, &KV[rowb]);
            cpa16(d + 4096 * 4, &KV[rowb + EMBED]);
        }
        cpa_commit();
    };

    // prologue: group A = Q (both halves) + KV stage 0; group B = KV stage 1
    #pragma unroll
    for (int p = 0; p < 16; p++) {
        int idx = tid + p * 128;           // 2048 float4
        int hh = idx >> 10;
        int r = (idx >> 4) & 63, c4 = (idx & 15) << 2;
        cpa16(sbase + (uint32_t)(AQ_OFF + hh * 4096 + asw(r, c4)) * 4,
              &Q[(size_t)(b * TQ + q0 + hh * 64 + r) * EMBED + h * HDIM + c4]);
    }
    {
        #pragma unroll
        for (int p = 0; p < 8; p++) {
            int idx = tid + p * 128;
            int r = idx >> 4, c4 = (idx & 15) << 2;
            size_t rowb = (size_t)(b * TK + r) * (2 * EMBED) + h * HDIM + c4;
            uint32_t d = sbase + (uint32_t)(AKV_OFF + asw(r, c4)) * 4;
            cpa16(d, &KV[rowb]);
            cpa16(d + 4096 * 4, &KV[rowb + EMBED]);
        }
        cpa_commit();
    }
    issue_kv(1, 64);

    uint32_t* Ps = (uint32_t*)smem + AP_OFF;

    float m[2][2], l[2][2], o[2][8][4];
    #pragma unroll
    for (int hh = 0; hh < 2; hh++) {
        m[hh][0] = m[hh][1] = -1e30f;
        l[hh][0] = l[hh][1] = 0.0f;
        #pragma unroll
        for (int ni = 0; ni < 8; ni++)
            #pragma unroll
            for (int j = 0; j < 4; j++) o[hh][ni][j] = 0.0f;
    }

    const int NT = TK / 64;   // 32

    for (int t = 0; t < NT; t++) {
        if (t < NT - 1) cpa_wait1(); else cpa_wait0();
        __syncthreads();

        const uint32_t* Ks = (const uint32_t*)smem + AKV_OFF + (t & 1) * 8192;
        const uint32_t* Vs = Ks + 4096;

        #pragma unroll
        for (int hh = 0; hh < 2; hh++) {
            const uint32_t* Qs = (const uint32_t*)smem + AQ_OFF + hh * 4096;

            // ---- S = Q @ K^T ----
            float s[8][4] = {};
            #pragma unroll
            for (int ks = 0; ks < 8; ks++) {
                const int k = ks * 8;
                uint32_t a[4];
                a[0] = Qs[asw(rb + gid,     k + tid4)];
                a[1] = Qs[asw(rb + gid + 8, k + tid4)];
                a[2] = Qs[asw(rb + gid,     k + tid4 + 4)];
                a[3] = Qs[asw(rb + gid + 8, k + tid4 + 4)];
                #pragma unroll
                for (int ni = 0; ni < 8; ni++) {
                    const int n = ni * 8;
                    uint32_t bfr[2];
                    bfr[0] = Ks[asw(n + gid, k + tid4)];
                    bfr[1] = Ks[asw(n + gid, k + tid4 + 4)];
                    mma_tf32(s[ni], a, bfr);
                }
            }

            // ---- online softmax ----
            float tmax0 = -1e30f, tmax1 = -1e30f;
            #pragma unroll
            for (int ni = 0; ni < 8; ni++) {
                tmax0 = fmaxf(tmax0, fmaxf(s[ni][0], s[ni][1]));
                tmax1 = fmaxf(tmax1, fmaxf(s[ni][2], s[ni][3]));
            }
            tmax0 = fmaxf(tmax0, __shfl_xor_sync(0xffffffffu, tmax0, 1, 4));
            tmax0 = fmaxf(tmax0, __shfl_xor_sync(0xffffffffu, tmax0, 2, 4));
            tmax1 = fmaxf(tmax1, __shfl_xor_sync(0xffffffffu, tmax1, 1, 4));
            tmax1 = fmaxf(tmax1, __shfl_xor_sync(0xffffffffu, tmax1, 2, 4));

            float mn0 = fmaxf(m[hh][0], tmax0), mn1 = fmaxf(m[hh][1], tmax1);
            float al0 = __expf(m[hh][0] - mn0), al1 = __expf(m[hh][1] - mn1);
            float rs0 = 0.0f, rs1 = 0.0f;
            #pragma unroll
            for (int ni = 0; ni < 8; ni++) {
                s[ni][0] = __expf(s[ni][0] - mn0);
                s[ni][1] = __expf(s[ni][1] - mn0);
                s[ni][2] = __expf(s[ni][2] - mn1);
                s[ni][3] = __expf(s[ni][3] - mn1);
                rs0 += s[ni][0] + s[ni][1];
                rs1 += s[ni][2] + s[ni][3];
            }
            rs0 += __shfl_xor_sync(0xffffffffu, rs0, 1, 4);
            rs0 += __shfl_xor_sync(0xffffffffu, rs0, 2, 4);
            rs1 += __shfl_xor_sync(0xffffffffu, rs1, 1, 4);
            rs1 += __shfl_xor_sync(0xffffffffu, rs1, 2, 4);
            l[hh][0] = l[hh][0] * al0 + rs0;  m[hh][0] = mn0;
            l[hh][1] = l[hh][1] * al1 + rs1;  m[hh][1] = mn1;
            #pragma unroll
            for (int ni = 0; ni < 8; ni++) {
                o[hh][ni][0] *= al0; o[hh][ni][1] *= al0;
                o[hh][ni][2] *= al1; o[hh][ni][3] *= al1;
            }

            // ---- stage P (warp-private rows) ----
            #pragma unroll
            for (int ni = 0; ni < 8; ni++) {
                int col = ni * 8 + 2 * tid4;
                Ps[asw(rb + gid, col)]         = f2tf(s[ni][0]);
                Ps[asw(rb + gid, col) + 1]     = f2tf(s[ni][1]);
                Ps[asw(rb + gid + 8, col)]     = f2tf(s[ni][2]);
                Ps[asw(rb + gid + 8, col) + 1] = f2tf(s[ni][3]);
            }
            __syncwarp();

            // ---- O += P @ V ----
            #pragma unroll
            for (int ks = 0; ks < 8; ks++) {
                const int k = ks * 8;
                uint32_t a[4];
                a[0] = Ps[asw(rb + gid,     k + tid4)];
                a[1] = Ps[asw(rb + gid + 8, k + tid4)];
                a[2] = Ps[asw(rb + gid,     k + tid4 + 4)];
                a[3] = Ps[asw(rb + gid + 8, k + tid4 + 4)];
                #pragma unroll
                for (int ni = 0; ni < 8; ni++) {
                    const int n = ni * 8;
                    uint32_t bfr[2];
                    bfr[0] = Vs[asw(k + tid4,     n + gid)];
                    bfr[1] = Vs[asw(k + tid4 + 4, n + gid)];
                    mma_tf32(o[hh][ni], a, bfr);
                }
            }
            __syncwarp();   // P reads done before other half overwrites
        }

        __syncthreads();
        if (t + 2 < NT) issue_kv(t & 1, (t + 2) * 64);
    }

    // ---- write O (normalize + tf32 round for O-proj) ----
    #pragma unroll
    for (int hh = 0; hh < 2; hh++) {
        float inv0 = 1.0f / l[hh][0], inv1 = 1.0f / l[hh][1];
        #pragma unroll
        for (int ni = 0; ni < 8; ni++) {
            int col = h * HDIM + ni * 8 + 2 * tid4;
            size_t r0 = (size_t)(b * TQ + q0 + hh * 64 + rb + gid) * EMBED;
            size_t r1 = (size_t)(b * TQ + q0 + hh * 64 + rb + gid + 8) * EMBED;
            float2 v0 = { f2tf_f(o[hh][ni][0] * inv0), f2tf_f(o[hh][ni][1] * inv0) };
            float2 v1 = { f2tf_f(o[hh][ni][2] * inv1), f2tf_f(o[hh][ni][3] * inv1) };
            *reinterpret_cast<float2*>(&O[r0 + col]) = v0;
            *reinterpret_cast<float2*>(&O[r1 + col]) = v1;
        }
    }
}

// ---------------------------------------------------------------------------
extern "C" void kernel_launch(void* const* d_in, const int* in_sizes, int n_in,
                              void* d_out, int out_size)
{
    const float* query   = (const float*)d_in[0];
    const float* context = (const float*)d_in[1];
    const float* Wq      = (const float*)d_in[2];
    const float* bq      = (const float*)d_in[3];
    const float* Wkv     = (const float*)d_in[4];
    const float* bkv     = (const float*)d_in[5];
    const float* Wo      = (const float*)d_in[6];
    const float* bo      = (const float*)d_in[7];
    float* out = (float*)d_out;

    float *qbuf, *kvbuf, *obuf, *rq, *rc, *rWq, *rWkv, *rWo;
    cudaGetSymbolAddress((void**)&qbuf,  g_Q);
    cudaGetSymbolAddress((void**)&kvbuf, g_KV);
    cudaGetSymbolAddress((void**)&obuf,  g_O);
    cudaGetSymbolAddress((void**)&rq,    g_rq);
    cudaGetSymbolAddress((void**)&rc,    g_rc);
    cudaGetSymbolAddress((void**)&rWq,   g_rWq);
    cudaGetSymbolAddress((void**)&rWkv,  g_rWkv);
    cudaGetSymbolAddress((void**)&rWo,   g_rWo);

    static bool attr_set = false;
    if (!attr_set) {
        cudaFuncSetAttribute(qkv_proj_kernel,
                             cudaFuncAttributeMaxDynamicSharedMemorySize, 3 * GSTG * 4);
        cudaFuncSetAttribute(oproj_kernel,
                             cudaFuncAttributeMaxDynamicSharedMemorySize, 3 * GSTG * 4);
        cudaFuncSetAttribute(attn_tc_kernel,
                             cudaFuncAttributeMaxDynamicSharedMemorySize, 114688);
        attr_set = true;
    }

    // ---- fused pre-round (one launch, 12M floats) ----
    round_all_kernel<<<3145728 / 256, 256>>>(
        (const float4*)query,   (float4*)rq,
        (const float4*)context, (float4*)rc,
        (const float4*)Wq,      (float4*)rWq,
        (const float4*)Wkv,     (float4*)rWkv,
        (const float4*)Wo,      (float4*)rWo);

    // ---- fused Q + KV projections ----
    qkv_proj_kernel<<<dim3(24, MROWS / 128), 256, 3 * GSTG * 4>>>(
        rq, rc, rWq, bq, rWkv, bkv, qbuf, kvbuf);

    // ---- attention core: 16 q-blocks x 32 (b,h) ----
    attn_tc_kernel<<<dim3(TQ / 128, BATCH * NHEADS), 128, 114688>>>(qbuf, kvbuf, obuf);

    // ---- output projection ----
    oproj_kernel<<<dim3(EMBED / 128, MROWS / 128), 256, 3 * GSTG * 4>>>(
        obuf, rWo, bo, out);
}